// round 14
// baseline (speedup 1.0000x reference)
#include <cuda_runtime.h>
#include <cuda_bf16.h>
#include <cstdint>

#define N_NODE 2048
#define DIM 256
#define D_SEQ 1280
#define HDH 384
#define N_HEAD 8
#define D_HEAD 48
#define B_GRAPH 8
#define S_LEN 1024
#define INV_SCALE 0.14433756729740643f  /* 1/sqrt(48) */

typedef __nv_bfloat16 bf16;

// ---------------- scratch (device globals; no allocs allowed) ----------------
__device__ __align__(128) float g_k[B_GRAPH * S_LEN * HDH];    // [b,s,h,d] fp32
__device__ __align__(128) float g_v[B_GRAPH * S_LEN * HDH];
__device__ __align__(128) float g_q[N_NODE * HDH];
__device__ __align__(128) float g_gpre[N_NODE * HDH];
__device__ __align__(128) float g_feat[N_NODE * HDH];
__device__ __align__(128) bf16  g_y[N_NODE * DIM];             // bf16 LN(node)
__device__ __align__(128) bf16  g_gf[N_NODE * HDH];            // bf16 gate*feat
__device__ __align__(128) bf16  g_wt[768 * D_SEQ];             // [n,k] bf16 [Wk|Wv]^T
__device__ __align__(128) bf16  g_wqg[768 * DIM];              // [n,k] bf16 [Wq|Wg]^T
__device__ __align__(128) bf16  g_wbt[DIM * HDH];              // [n,k] bf16 Wback^T
__device__ __align__(128) bf16  g_embt[8192 * D_SEQ];          // bf16 emb
__device__ int   g_numTiles;
__device__ int   g_tile_b[80];
__device__ int   g_tile_n0[80];
__device__ int   g_tile_nv[80];

__device__ __forceinline__ uint32_t smem_u32(const void* p) {
    uint32_t a;
    asm("{ .reg .u64 t; cvta.to.shared.u64 t, %1; cvt.u32.u64 %0, t; }"
        : "=r"(a) : "l"(p));
    return a;
}
#define CP16(dst, src) \
    asm volatile("cp.async.cg.shared.global [%0], [%1], 16;" \
                 :: "r"(dst), "l"(src) : "memory")
#define CP_COMMIT() asm volatile("cp.async.commit_group;" ::: "memory")
#define CP_WAIT1()  asm volatile("cp.async.wait_group 1;" ::: "memory")
#define CP_WAIT0()  asm volatile("cp.async.wait_group 0;" ::: "memory")

// ---------------- kernel 0: segment batch, build node tiles ------------------
__global__ void setup_kernel(const void* batch_raw) {
    __shared__ int cnt[8];
    __shared__ int ok32;
    int tid = threadIdx.x;
    if (tid < 8) cnt[tid] = 0;
    if (tid == 0) ok32 = 1;
    __syncthreads();
    const int* b32 = (const int*)batch_raw;
    int bad = 0;
    for (int i = tid; i < N_NODE; i += blockDim.x) {
        int v = b32[i];
        if (v < 0 || v >= 8) bad = 1;
        if (i + 1 < N_NODE && b32[i + 1] < v) bad = 1;
    }
    if (bad) ok32 = 0;
    __syncthreads();
    const long long* b64 = (const long long*)batch_raw;
    for (int i = tid; i < N_NODE; i += blockDim.x) {
        int v = ok32 ? b32[i] : (int)b64[i];
        v = min(max(v, 0), 7);
        atomicAdd(&cnt[v], 1);
    }
    __syncthreads();
    if (tid == 0) {
        int off = 0, t = 0;
        for (int b = 0; b < 8; b++) {
            int nb = cnt[b];
            for (int s = 0; s < nb; s += 32) {
                g_tile_b[t] = b;
                g_tile_n0[t] = off + s;
                g_tile_nv[t] = min(32, nb - s);
                t++;
            }
            off += nb;
        }
        g_numTiles = t;
    }
}

// ---------------- kernel 0a: convert emb -> bf16 g_embt ----------------------
__global__ void __launch_bounds__(256) cvt_kernel(const float* __restrict__ emb) {
    int i = blockIdx.x * 256 + threadIdx.x;   // 8 floats / thread; grid exact
    float4 v0 = ((const float4*)emb)[2 * i];
    float4 v1 = ((const float4*)emb)[2 * i + 1];
    bf16 o[8];
    o[0] = __float2bfloat16_rn(v0.x); o[1] = __float2bfloat16_rn(v0.y);
    o[2] = __float2bfloat16_rn(v0.z); o[3] = __float2bfloat16_rn(v0.w);
    o[4] = __float2bfloat16_rn(v1.x); o[5] = __float2bfloat16_rn(v1.y);
    o[6] = __float2bfloat16_rn(v1.z); o[7] = __float2bfloat16_rn(v1.w);
    ((uint4*)g_embt)[i] = *(uint4*)o;
}

// ------------ kernel 0b: generic transpose + bf16 convert --------------------
// src[R][C] row-major fp32 -> dst[(rowOff+c)][r] bf16, dst row stride = R.
__global__ void __launch_bounds__(256) transpose_bf16(
    const float* __restrict__ src, int R, int C,
    bf16* __restrict__ dst, int rowOff)
{
    __shared__ float tile[32][33];
    int kb = blockIdx.x * 32, nb = blockIdx.y * 32;   // kb over R, nb over C
    int tx = threadIdx.x & 31, ty = threadIdx.x >> 5; // 32 x 8
#pragma unroll
    for (int i = 0; i < 4; i++)
        tile[ty + i * 8][tx] = src[(size_t)(kb + ty + i * 8) * C + nb + tx];
    __syncthreads();
#pragma unroll
    for (int i = 0; i < 4; i++)
        dst[(size_t)(rowOff + nb + ty + i * 8) * R + kb + tx] =
            __float2bfloat16_rn(tile[tx][ty + i * 8]);
}

// ---------------- kernel 1: layernorm -> g_y (bf16) --------------------------
__global__ void __launch_bounds__(256) ln_kernel(
    const float* __restrict__ node,
    const float* __restrict__ ln_g, const float* __restrict__ ln_b)
{
    int w = threadIdx.x >> 5, lane = threadIdx.x & 31;
    int n = blockIdx.x * 8 + w;
    float xv[8];
    float sx = 0.f, sxx = 0.f;
#pragma unroll
    for (int i = 0; i < 8; i++) {
        float x = node[n * DIM + lane + i * 32];
        xv[i] = x; sx += x; sxx += x * x;
    }
#pragma unroll
    for (int o = 16; o > 0; o >>= 1) {
        sx  += __shfl_xor_sync(0xffffffffu, sx, o);
        sxx += __shfl_xor_sync(0xffffffffu, sxx, o);
    }
    float mu = sx * (1.f / DIM);
    float var = sxx * (1.f / DIM) - mu * mu;
    float inv = rsqrtf(var + 1e-5f);
#pragma unroll
    for (int i = 0; i < 8; i++) {
        int d = lane + i * 32;
        g_y[n * DIM + d] =
            __float2bfloat16_rn((xv[i] - mu) * inv * ln_g[d] + ln_b[d]);
    }
}

// ---------------- kernel 1b: gate*feat -> g_gf (bf16) ------------------------
__global__ void __launch_bounds__(256) gf_kernel() {
    int i = blockIdx.x * 256 + threadIdx.x;   // 8 elems / thread; grid exact
    float4 g0 = ((const float4*)g_gpre)[2 * i];
    float4 g1 = ((const float4*)g_gpre)[2 * i + 1];
    float4 f0 = ((const float4*)g_feat)[2 * i];
    float4 f1 = ((const float4*)g_feat)[2 * i + 1];
    bf16 o[8];
    o[0] = __float2bfloat16_rn(f0.x / (1.f + __expf(-g0.x)));
    o[1] = __float2bfloat16_rn(f0.y / (1.f + __expf(-g0.y)));
    o[2] = __float2bfloat16_rn(f0.z / (1.f + __expf(-g0.z)));
    o[3] = __float2bfloat16_rn(f0.w / (1.f + __expf(-g0.w)));
    o[4] = __float2bfloat16_rn(f1.x / (1.f + __expf(-g1.x)));
    o[5] = __float2bfloat16_rn(f1.y / (1.f + __expf(-g1.y)));
    o[6] = __float2bfloat16_rn(f1.z / (1.f + __expf(-g1.z)));
    o[7] = __float2bfloat16_rn(f1.w / (1.f + __expf(-g1.w)));
    ((uint4*)g_gf)[i] = *(uint4*)o;
}

// ---------------- unified BF16 mma.sync GEMM ---------------------------------
// CTA 128x64, 8 warps (4m x 2n), warp 32x32 = 2x4 m16n8k16 tiles, 2-stage
// cp.async. A[M,K], B[N,K] bf16 row-major K-major. K chunk = 64 elems = 128B.
// Smem row = 32 u32 (bf16 pairs), stride 36 (conflict-free, same as tf32 ver).
// EPI 0: split cols at 384 -> p0 (g_k) / p1 (g_v), fp32 stride HDH
// EPI 1: split cols at 384 -> p0 (g_q) / p1 (g_gpre, + bias q0)
// EPI 2: p0[r*256+c] = q0[r*256+c] + acc + q1[c]
#define KV_STRIDE 36
#define KV_STAGE_U32 ((128 + 64) * KV_STRIDE)   // 6912 u32 = 27648 B
#define KV_SMEM_BYTES (2 * KV_STAGE_U32 * 4)    // 55296 B

#define MMA_BF16(c, a, b) \
    asm volatile("mma.sync.aligned.m16n8k16.row.col.f32.bf16.bf16.f32 " \
        "{%0,%1,%2,%3}, {%4,%5,%6,%7}, {%8,%9}, {%0,%1,%2,%3};" \
        : "+f"((c)[0]), "+f"((c)[1]), "+f"((c)[2]), "+f"((c)[3]) \
        : "r"((a)[0]), "r"((a)[1]), "r"((a)[2]), "r"((a)[3]), \
          "r"((b)[0]), "r"((b)[1]))

template<int CHUNKS, int EPI>
__global__ void __launch_bounds__(256, 4) gemm_bf16(
    const bf16* __restrict__ A, const bf16* __restrict__ B,
    float* __restrict__ p0, float* __restrict__ p1,
    const float* __restrict__ q0, const float* __restrict__ q1)
{
    const int K = CHUNKS * 64;
    extern __shared__ uint32_t skv[];
    uint32_t sb = smem_u32(skv);

    int tid = threadIdx.x;
    int wid = tid >> 5, lane = tid & 31;
    int warp_m = wid & 3, warp_n = wid >> 2;
    int lr = lane >> 2, lc = lane & 3;

    int m0 = (int)blockIdx.x * 128;
    int n0 = (int)blockIdx.y * 64;

    int arow = tid >> 1, ahalf = tid & 1;                 // A: 4 cp16 / thread
    const char* gA = (const char*)(A + (size_t)(m0 + arow) * K) + ahalf * 64;
    int brow = tid >> 2, bq = tid & 3;                    // B: 2 cp16 / thread
    const char* gB = (const char*)(B + (size_t)(n0 + brow) * K) + bq * 32;
    uint32_t dA = sb + (uint32_t)(arow * KV_STRIDE + ahalf * 16) * 4;
    uint32_t dB = sb + (uint32_t)(128 * KV_STRIDE + brow * KV_STRIDE + bq * 8) * 4;

    float acc[2][4][4];
#pragma unroll
    for (int mt = 0; mt < 2; mt++)
#pragma unroll
        for (int nt = 0; nt < 4; nt++)
#pragma unroll
            for (int i = 0; i < 4; i++) acc[mt][nt][i] = 0.f;

    // prologue: chunks 0,1  (chunk stride = 128 bytes)
#pragma unroll
    for (int st = 0; st < 2; st++) {
        uint32_t off = st * (KV_STAGE_U32 * 4);
        int kb = st * 128;
#pragma unroll
        for (int j = 0; j < 4; j++) CP16(dA + off + j * 16, gA + kb + j * 16);
#pragma unroll
        for (int j = 0; j < 2; j++) CP16(dB + off + j * 16, gB + kb + j * 16);
        CP_COMMIT();
    }

    for (int ch = 0; ch < CHUNKS; ch++) {
        CP_WAIT1();
        __syncthreads();
        const uint32_t* sA = skv + (ch & 1) * KV_STAGE_U32;
        const uint32_t* sBp = sA + 128 * KV_STRIDE;

#pragma unroll
        for (int ks = 0; ks < 4; ks++) {
            int kk = ks * 8;
            uint32_t af[2][4];
#pragma unroll
            for (int mt = 0; mt < 2; mt++) {
                int r = warp_m * 32 + mt * 16 + lr;
                int c = kk + lc;
                af[mt][0] = sA[r * KV_STRIDE + c];
                af[mt][1] = sA[(r + 8) * KV_STRIDE + c];
                af[mt][2] = sA[r * KV_STRIDE + c + 4];
                af[mt][3] = sA[(r + 8) * KV_STRIDE + c + 4];
            }
            uint32_t bf[4][2];
#pragma unroll
            for (int nt = 0; nt < 4; nt++) {
                int n = warp_n * 32 + nt * 8 + lr;
                bf[nt][0] = sBp[n * KV_STRIDE + kk + lc];
                bf[nt][1] = sBp[n * KV_STRIDE + kk + lc + 4];
            }
#pragma unroll
            for (int mt = 0; mt < 2; mt++)
#pragma unroll
                for (int nt = 0; nt < 4; nt++)
                    MMA_BF16(acc[mt][nt], af[mt], bf[nt]);
        }
        __syncthreads();
        if (ch < CHUNKS - 2) {
            uint32_t off = (ch & 1) * (KV_STAGE_U32 * 4);
            int kb = (ch + 2) * 128;
#pragma unroll
            for (int j = 0; j < 4; j++) CP16(dA + off + j * 16, gA + kb + j * 16);
#pragma unroll
            for (int j = 0; j < 2; j++) CP16(dB + off + j * 16, gB + kb + j * 16);
        }
        CP_COMMIT();
    }

    // epilogue
#pragma unroll
    for (int mt = 0; mt < 2; mt++) {
        int r = m0 + warp_m * 32 + mt * 16 + lr;
#pragma unroll
        for (int nt = 0; nt < 4; nt++) {
            int cn = n0 + warp_n * 32 + nt * 8 + 2 * lc;
            float2 lo = make_float2(acc[mt][nt][0], acc[mt][nt][1]);
            float2 hi = make_float2(acc[mt][nt][2], acc[mt][nt][3]);
            if (EPI == 0) {          // k | v
                float* dst = (n0 < 384) ? p0 : p1;
                int c = (n0 < 384) ? cn : cn - 384;
                *(float2*)&dst[(size_t)r * HDH + c] = lo;
                *(float2*)&dst[(size_t)(r + 8) * HDH + c] = hi;
            } else if (EPI == 1) {   // q | gpre(+bg)
                if (n0 < 384) {
                    *(float2*)&p0[(size_t)r * HDH + cn] = lo;
                    *(float2*)&p0[(size_t)(r + 8) * HDH + cn] = hi;
                } else {
                    int c = cn - 384;
                    float2 bb = *(const float2*)&q0[c];
                    lo.x += bb.x; lo.y += bb.y; hi.x += bb.x; hi.y += bb.y;
                    *(float2*)&p1[(size_t)r * HDH + c] = lo;
                    *(float2*)&p1[(size_t)(r + 8) * HDH + c] = hi;
                }
            } else {                 // out = node + acc + bback
                float2 bb = *(const float2*)&q1[cn];
                float2 n1 = *(const float2*)&q0[(size_t)r * DIM + cn];
                float2 n2 = *(const float2*)&q0[(size_t)(r + 8) * DIM + cn];
                lo.x += bb.x + n1.x; lo.y += bb.y + n1.y;
                hi.x += bb.x + n2.x; hi.y += bb.y + n2.y;
                *(float2*)&p0[(size_t)r * DIM + cn] = lo;
                *(float2*)&p0[(size_t)(r + 8) * DIM + cn] = hi;
            }
        }
    }
}

// ---------------- kernel 3: attention (flash-style, cp.async 2-stage) --------
#define ATTN_SMEM_BYTES (25216 * 4)

__global__ void __launch_bounds__(256) attn_kernel(const int* __restrict__ mask)
{
    extern __shared__ float sm[];
    int*   sMaskAll = (int*)(sm + 24576);
    float* sML  = sm + 24704;
    float* cAcc = sm;

    int t = blockIdx.x >> 2;
    if (t >= g_numTiles) return;
    int hp = blockIdx.x & 3;
    int b = g_tile_b[t], n0 = g_tile_n0[t], nv = g_tile_nv[t];
    int tid = threadIdx.x, w = tid >> 5, lane = tid & 31;
    int hl = w & 1, st = w >> 1;
    int h = hp * 2 + hl;

    float qv[48];
    if (lane < nv) {
        const float4* qp = (const float4*)&g_q[(n0 + lane) * HDH + h * D_HEAD];
#pragma unroll
        for (int i = 0; i < 12; i++) {
            float4 v = qp[i];
            qv[4 * i] = v.x; qv[4 * i + 1] = v.y; qv[4 * i + 2] = v.z; qv[4 * i + 3] = v.w;
        }
    } else {
#pragma unroll
        for (int i = 0; i < 48; i++) qv[i] = 0.f;
    }

    float m = -1e30f, l = 0.f;
    float acc[48];
#pragma unroll
    for (int i = 0; i < 48; i++) acc[i] = 0.f;

    uint32_t sb = smem_u32(sm);
    const char* Kg = (const char*)g_k;
    const char* Vg = (const char*)g_v;

    uint32_t so16[6];
    long     gOff[6];
#pragma unroll
    for (int q8 = 0; q8 < 6; q8++) {
        int idx = tid + q8 * 256;
        int row = idx / 24, c4 = idx % 24;
        so16[q8] = (uint32_t)(row * 24 + c4) * 16;
        gOff[q8] = ((long)(b * S_LEN + row) * 96 + hp * 24 + c4) * 16;
    }
    const char* maskSrc = (const char*)(mask + (long)b * S_LEN + tid * 4);

#pragma unroll
    for (int cj = 0; cj < 2; cj++) {
        uint32_t kb = sb + (uint32_t)(cj * 12288) * 4;
        long chOff = (long)cj * 64 * 96 * 16;
#pragma unroll
        for (int q8 = 0; q8 < 6; q8++) {
            CP16(kb + so16[q8], Kg + gOff[q8] + chOff);
            CP16(kb + 6144 * 4 + so16[q8], Vg + gOff[q8] + chOff);
        }
        if (tid < 16)
            CP16(sb + (uint32_t)(24576 + cj * 64) * 4 + tid * 16,
                 maskSrc + (long)cj * 256);
        CP_COMMIT();
    }

    for (int ci = 0; ci < 16; ci++) {
        CP_WAIT1();
        __syncthreads();
        const float* sK = sm + (ci & 1) * 12288;
        const float* sV = sK + 6144;
        const int* sMask = sMaskAll + (ci & 1) * 64;

        float sc16[16];
#pragma unroll 4
        for (int i = 0; i < 16; i++) {
            int s = 4 * i + st;
            if (sMask[s]) {
                const float4* kr = (const float4*)&sK[s * 96 + hl * 48];
                float d0 = 0.f, d1 = 0.f, d2 = 0.f, d3 = 0.f;
#pragma unroll
                for (int i4 = 0; i4 < 12; i4++) {
                    float4 kk = kr[i4];
                    d0 = fmaf(qv[4 * i4 + 0], kk.x, d0);
                    d1 = fmaf(qv[4 * i4 + 1], kk.y, d1);
                    d2 = fmaf(qv[4 * i4 + 2], kk.z, d2);
                    d3 = fmaf(qv[4 * i4 + 3], kk.w, d3);
                }
                sc16[i] = ((d0 + d1) + (d2 + d3)) * INV_SCALE;
            } else {
                sc16[i] = -1e30f;
            }
        }
        float mc = -1e30f;
#pragma unroll
        for (int i = 0; i < 16; i++) mc = fmaxf(mc, sc16[i]);
        if (mc > -1e29f) {
            float mn = fmaxf(m, mc);
            float f = __expf(m - mn);
            l *= f;
#pragma unroll
            for (int d = 0; d < 48; d++) acc[d] *= f;
            m = mn;
#pragma unroll 2
            for (int i = 0; i < 16; i++) {
                if (sc16[i] > -1e29f) {
                    float p = __expf(sc16[i] - m);
                    l += p;
                    const float4* vr = (const float4*)&sV[(4 * i + st) * 96 + hl * 48];
#pragma unroll
                    for (int i4 = 0; i4 < 12; i4++) {
                        float4 vv = vr[i4];
                        acc[4 * i4 + 0] = fmaf(p, vv.x, acc[4 * i4 + 0]);
                        acc[4 * i4 + 1] = fmaf(p, vv.y, acc[4 * i4 + 1]);
                        acc[4 * i4 + 2] = fmaf(p, vv.z, acc[4 * i4 + 2]);
                        acc[4 * i4 + 3] = fmaf(p, vv.w, acc[4 * i4 + 3]);
                    }
                }
            }
        }
        __syncthreads();
        if (ci < 14) {
            int cj = ci + 2;
            uint32_t kb = sb + (uint32_t)((cj & 1) * 12288) * 4;
            long chOff = (long)cj * 64 * 96 * 16;
#pragma unroll
            for (int q8 = 0; q8 < 6; q8++) {
                CP16(kb + so16[q8], Kg + gOff[q8] + chOff);
                CP16(kb + 6144 * 4 + so16[q8], Vg + gOff[q8] + chOff);
            }
            if (tid < 16)
                CP16(sb + (uint32_t)(24576 + (cj & 1) * 64) * 4 + tid * 16,
                     maskSrc + (long)cj * 256);
        }
        CP_COMMIT();
    }
    CP_WAIT0();
    __syncthreads();

    {
        int r = (st * 32 + lane) * 2 + hl;
        sML[r * 2 + 0] = m;
        sML[r * 2 + 1] = l;
#pragma unroll
        for (int d = 0; d < 48; d++) cAcc[r * 48 + d] = acc[d];
    }
    __syncthreads();

    if (tid < 64) {
        int j = tid >> 1, hlf = tid & 1;
        int hf = hp * 2 + hlf;
        float M = -1e30f;
#pragma unroll
        for (int s = 0; s < 4; s++)
            M = fmaxf(M, sML[((s * 32 + j) * 2 + hlf) * 2]);
        float L = 0.f, e[4];
#pragma unroll
        for (int s = 0; s < 4; s++) {
            float ms = sML[((s * 32 + j) * 2 + hlf) * 2];
            float ls = sML[((s * 32 + j) * 2 + hlf) * 2 + 1];
            e[s] = __expf(ms - M);
            L += ls * e[s];
        }
        float invL = 1.f / (L + 1e-9f);
        if (j < nv) {
            float* outp = &g_feat[(n0 + j) * HDH + hf * D_HEAD];
            for (int d = 0; d < 48; d++) {
                float F = 0.f;
#pragma unroll
                for (int s = 0; s < 4; s++)
                    F += cAcc[((s * 32 + j) * 2 + hlf) * 48 + d] * e[s];
                outp[d] = F * invL;
            }
        }
    }
}

// ---------------- launch -----------------------------------------------------
extern "C" void kernel_launch(void* const* d_in, const int* in_sizes, int n_in,
                              void* d_out, int out_size) {
    const float* node  = (const float*)d_in[0];
    const float* emb   = (const float*)d_in[1];
    const int*   mask  = (const int*)d_in[2];
    const void*  batch = d_in[3];
    const float* ln_g  = (const float*)d_in[4];
    const float* ln_b  = (const float*)d_in[5];
    const float* Wq    = (const float*)d_in[6];
    const float* Wk    = (const float*)d_in[7];
    const float* Wv    = (const float*)d_in[8];
    const float* Wg    = (const float*)d_in[9];
    const float* bg    = (const float*)d_in[10];
    const float* Wback = (const float*)d_in[11];
    const float* bback = (const float*)d_in[12];
    float* out = (float*)d_out;

    float *p_q, *p_gpre, *p_k, *p_v;
    bf16 *p_y, *p_gf, *p_wt, *p_wqg, *p_wbt, *p_embt;
    cudaGetSymbolAddress((void**)&p_q,    g_q);
    cudaGetSymbolAddress((void**)&p_gpre, g_gpre);
    cudaGetSymbolAddress((void**)&p_k,    g_k);
    cudaGetSymbolAddress((void**)&p_v,    g_v);
    cudaGetSymbolAddress((void**)&p_y,    g_y);
    cudaGetSymbolAddress((void**)&p_gf,   g_gf);
    cudaGetSymbolAddress((void**)&p_wt,   g_wt);
    cudaGetSymbolAddress((void**)&p_wqg,  g_wqg);
    cudaGetSymbolAddress((void**)&p_wbt,  g_wbt);
    cudaGetSymbolAddress((void**)&p_embt, g_embt);

    cudaFuncSetAttribute(attn_kernel,
                         cudaFuncAttributeMaxDynamicSharedMemorySize, ATTN_SMEM_BYTES);
    cudaFuncSetAttribute(gemm_bf16<4, 1>,
                         cudaFuncAttributeMaxDynamicSharedMemorySize, KV_SMEM_BYTES);
    cudaFuncSetAttribute(gemm_bf16<20, 0>,
                         cudaFuncAttributeMaxDynamicSharedMemorySize, KV_SMEM_BYTES);
    cudaFuncSetAttribute(gemm_bf16<6, 2>,
                         cudaFuncAttributeMaxDynamicSharedMemorySize, KV_SMEM_BYTES);

    setup_kernel<<<1, 256>>>(batch);
    cvt_kernel<<<8192 * D_SEQ / (8 * 256), 256>>>(emb);
    // B-operand transposes (bf16, [n][k] layout)
    transpose_bf16<<<dim3(DIM / 32, HDH / 32), 256>>>(Wq, DIM, HDH, p_wqg, 0);
    transpose_bf16<<<dim3(DIM / 32, HDH / 32), 256>>>(Wg, DIM, HDH, p_wqg, 384);
    transpose_bf16<<<dim3(D_SEQ / 32, HDH / 32), 256>>>(Wk, D_SEQ, HDH, p_wt, 0);
    transpose_bf16<<<dim3(D_SEQ / 32, HDH / 32), 256>>>(Wv, D_SEQ, HDH, p_wt, 384);
    transpose_bf16<<<dim3(HDH / 32, DIM / 32), 256>>>(Wback, HDH, DIM, p_wbt, 0);
    ln_kernel<<<N_NODE / 8, 256>>>(node, ln_g, ln_b);
    // GEMM1: [q|gpre] = y @ [Wq|Wg]  (+bg on gpre half)
    gemm_bf16<4, 1><<<dim3(16, 12), 256, KV_SMEM_BYTES>>>(
        p_y, p_wqg, p_q, p_gpre, bg, nullptr);
    // GEMM2: [k|v] = embt @ [Wk|Wv]
    gemm_bf16<20, 0><<<dim3(64, 12), 256, KV_SMEM_BYTES>>>(
        p_embt, p_wt, p_k, p_v, nullptr, nullptr);
    attn_kernel<<<288, 256, ATTN_SMEM_BYTES>>>(mask);
    gf_kernel<<<N_NODE * HDH / (8 * 256), 256>>>();
    // GEMM3: out = node + (gate*feat) @ Wback + bback
    gemm_bf16<6, 2><<<dim3(16, 4), 256, KV_SMEM_BYTES>>>(
        p_gf, p_wbt, out, nullptr, node, bback);
}

// round 16
// speedup vs baseline: 1.2922x; 1.2922x over previous
#include <cuda_runtime.h>
#include <cuda_bf16.h>
#include <cstdint>

#define N_NODE 2048
#define DIM 256
#define D_SEQ 1280
#define HDH 384
#define N_HEAD 8
#define D_HEAD 48
#define B_GRAPH 8
#define S_LEN 1024
#define INV_SCALE 0.14433756729740643f

typedef __nv_bfloat16 bf16;

// ---------------- scratch ----------------------------------------------------
__device__ __align__(128) float g_k[(8192 + 64) * HDH];   // compacted K fp32
__device__ __align__(128) float g_v[(8192 + 64) * HDH];   // compacted V fp32
__device__ __align__(128) float g_q[N_NODE * HDH];
__device__ __align__(128) float g_gpre[N_NODE * HDH];
__device__ __align__(128) float g_feat[N_NODE * HDH];
__device__ __align__(128) bf16  g_y[N_NODE * DIM];
__device__ __align__(128) bf16  g_gf[N_NODE * HDH];
__device__ __align__(128) bf16  g_wt[768 * D_SEQ];
__device__ __align__(128) bf16  g_wqg[768 * DIM];
__device__ __align__(128) bf16  g_wbt[DIM * HDH];
__device__ __align__(128) bf16  g_embt[8192 * D_SEQ];     // compacted bf16 emb
__device__ int g_pos[8192];
__device__ int g_off[B_GRAPH];
__device__ int g_cnt[B_GRAPH];
__device__ int g_mTotal;
__device__ int g_numTiles;
__device__ int g_tile_b[80];
__device__ int g_tile_n0[80];
__device__ int g_tile_nv[80];

__device__ __forceinline__ uint32_t smem_u32(const void* p) {
    uint32_t a;
    asm("{ .reg .u64 t; cvta.to.shared.u64 t, %1; cvt.u32.u64 %0, t; }"
        : "=r"(a) : "l"(p));
    return a;
}
#define CP16(dst, src) \
    asm volatile("cp.async.cg.shared.global [%0], [%1], 16;" \
                 :: "r"(dst), "l"(src) : "memory")
#define CP_COMMIT() asm volatile("cp.async.commit_group;" ::: "memory")
#define CP_WAIT1()  asm volatile("cp.async.wait_group 1;" ::: "memory")
#define CP_WAIT0()  asm volatile("cp.async.wait_group 0;" ::: "memory")

// ---------------- kernel 0: batch tiles + mask compaction --------------------
__global__ void setup_kernel(const void* batch_raw, const int* __restrict__ mask) {
    __shared__ int cnt[8];
    __shared__ int mcnt[8], moff[8];
    __shared__ int ok32;
    int tid = threadIdx.x, w = tid >> 5, lane = tid & 31;
    if (tid < 8) cnt[tid] = 0;
    if (tid == 0) ok32 = 1;
    __syncthreads();
    const int* b32 = (const int*)batch_raw;
    int bad = 0;
    for (int i = tid; i < N_NODE; i += 256) {
        int v = b32[i];
        if (v < 0 || v >= 8) bad = 1;
        if (i + 1 < N_NODE && b32[i + 1] < v) bad = 1;
    }
    if (bad) ok32 = 0;
    __syncthreads();
    const long long* b64 = (const long long*)batch_raw;
    for (int i = tid; i < N_NODE; i += 256) {
        int v = ok32 ? b32[i] : (int)b64[i];
        v = min(max(v, 0), 7);
        atomicAdd(&cnt[v], 1);
    }
    // mask count: warp w -> graph w
    {
        int c = 0;
        for (int g = 0; g < 32; g++) {
            int v = mask[w * S_LEN + g * 32 + lane] != 0;
            c += __popc(__ballot_sync(0xffffffffu, v));
        }
        if (lane == 0) mcnt[w] = c;
    }
    __syncthreads();
    if (tid == 0) {
        int off = 0, t = 0;
        for (int b = 0; b < 8; b++) {
            int nb = cnt[b];
            for (int s = 0; s < nb; s += 32) {
                g_tile_b[t] = b;
                g_tile_n0[t] = off + s;
                g_tile_nv[t] = min(32, nb - s);
                t++;
            }
            off += nb;
        }
        g_numTiles = t;
        int o = 0;
        for (int b = 0; b < 8; b++) {
            moff[b] = o; g_off[b] = o; g_cnt[b] = mcnt[b]; o += mcnt[b];
        }
        g_mTotal = o;
    }
    __syncthreads();
    // positions: warp w -> graph w (stable)
    {
        int o = moff[w];
        for (int g = 0; g < 32; g++) {
            int idx = w * S_LEN + g * 32 + lane;
            int v = mask[idx] != 0;
            uint32_t bal = __ballot_sync(0xffffffffu, v);
            g_pos[idx] = v ? (o + __popc(bal & ((1u << lane) - 1))) : -1;
            o += __popc(bal);
        }
    }
}

// ---------------- kernel 0a: compacted emb -> bf16 ---------------------------
__global__ void __launch_bounds__(160) cvt_kernel(const float* __restrict__ emb) {
    int r = blockIdx.x;
    int p = g_pos[r];
    if (p < 0) return;
    int t = threadIdx.x;  // 0..159
    const float4* src = (const float4*)(emb + (size_t)r * D_SEQ);
    float4 v0 = src[2 * t], v1 = src[2 * t + 1];
    bf16 o[8];
    o[0] = __float2bfloat16_rn(v0.x); o[1] = __float2bfloat16_rn(v0.y);
    o[2] = __float2bfloat16_rn(v0.z); o[3] = __float2bfloat16_rn(v0.w);
    o[4] = __float2bfloat16_rn(v1.x); o[5] = __float2bfloat16_rn(v1.y);
    o[6] = __float2bfloat16_rn(v1.z); o[7] = __float2bfloat16_rn(v1.w);
    ((uint4*)(g_embt + (size_t)p * D_SEQ))[t] = *(uint4*)o;
}

// ------------ kernel 0b: transpose + bf16 ------------------------------------
__global__ void __launch_bounds__(256) transpose_bf16(
    const float* __restrict__ src, int R, int C,
    bf16* __restrict__ dst, int rowOff)
{
    __shared__ float tile[32][33];
    int kb = blockIdx.x * 32, nb = blockIdx.y * 32;
    int tx = threadIdx.x & 31, ty = threadIdx.x >> 5;
#pragma unroll
    for (int i = 0; i < 4; i++)
        tile[ty + i * 8][tx] = src[(size_t)(kb + ty + i * 8) * C + nb + tx];
    __syncthreads();
#pragma unroll
    for (int i = 0; i < 4; i++)
        dst[(size_t)(rowOff + nb + ty + i * 8) * R + kb + tx] =
            __float2bfloat16_rn(tile[tx][ty + i * 8]);
}

// ---------------- kernel 1: layernorm -> g_y (bf16) --------------------------
__global__ void __launch_bounds__(256) ln_kernel(
    const float* __restrict__ node,
    const float* __restrict__ ln_g, const float* __restrict__ ln_b)
{
    int w = threadIdx.x >> 5, lane = threadIdx.x & 31;
    int n = blockIdx.x * 8 + w;
    float xv[8];
    float sx = 0.f, sxx = 0.f;
#pragma unroll
    for (int i = 0; i < 8; i++) {
        float x = node[n * DIM + lane + i * 32];
        xv[i] = x; sx += x; sxx += x * x;
    }
#pragma unroll
    for (int o = 16; o > 0; o >>= 1) {
        sx  += __shfl_xor_sync(0xffffffffu, sx, o);
        sxx += __shfl_xor_sync(0xffffffffu, sxx, o);
    }
    float mu = sx * (1.f / DIM);
    float var = sxx * (1.f / DIM) - mu * mu;
    float inv = rsqrtf(var + 1e-5f);
#pragma unroll
    for (int i = 0; i < 8; i++) {
        int d = lane + i * 32;
        g_y[n * DIM + d] =
            __float2bfloat16_rn((xv[i] - mu) * inv * ln_g[d] + ln_b[d]);
    }
}

// ---------------- kernel 1b: gate*feat -> g_gf (bf16) ------------------------
__global__ void __launch_bounds__(256) gf_kernel() {
    int i = blockIdx.x * 256 + threadIdx.x;
    float4 g0 = ((const float4*)g_gpre)[2 * i];
    float4 g1 = ((const float4*)g_gpre)[2 * i + 1];
    float4 f0 = ((const float4*)g_feat)[2 * i];
    float4 f1 = ((const float4*)g_feat)[2 * i + 1];
    bf16 o[8];
    o[0] = __float2bfloat16_rn(f0.x / (1.f + __expf(-g0.x)));
    o[1] = __float2bfloat16_rn(f0.y / (1.f + __expf(-g0.y)));
    o[2] = __float2bfloat16_rn(f0.z / (1.f + __expf(-g0.z)));
    o[3] = __float2bfloat16_rn(f0.w / (1.f + __expf(-g0.w)));
    o[4] = __float2bfloat16_rn(f1.x / (1.f + __expf(-g1.x)));
    o[5] = __float2bfloat16_rn(f1.y / (1.f + __expf(-g1.y)));
    o[6] = __float2bfloat16_rn(f1.z / (1.f + __expf(-g1.z)));
    o[7] = __float2bfloat16_rn(f1.w / (1.f + __expf(-g1.w)));
    ((uint4*)g_gf)[i] = *(uint4*)o;
}

// ---------------- unified BF16 mma.sync GEMM ---------------------------------
#define KV_STRIDE 36
#define KV_STAGE_U32 ((128 + 64) * KV_STRIDE)
#define KV_SMEM_BYTES (2 * KV_STAGE_U32 * 4)

#define MMA_BF16(c, a, b) \
    asm volatile("mma.sync.aligned.m16n8k16.row.col.f32.bf16.bf16.f32 " \
        "{%0,%1,%2,%3}, {%4,%5,%6,%7}, {%8,%9}, {%0,%1,%2,%3};" \
        : "+f"((c)[0]), "+f"((c)[1]), "+f"((c)[2]), "+f"((c)[3]) \
        : "r"((a)[0]), "r"((a)[1]), "r"((a)[2]), "r"((a)[3]), \
          "r"((b)[0]), "r"((b)[1]))

template<int CHUNKS, int EPI>
__global__ void __launch_bounds__(256, 4) gemm_bf16(
    const bf16* __restrict__ A, const bf16* __restrict__ B,
    float* __restrict__ p0, float* __restrict__ p1,
    const float* __restrict__ q0, const float* __restrict__ q1)
{
    const int K = CHUNKS * 64;
    int m0 = (int)blockIdx.x * 128;
    if (EPI == 0 && m0 >= g_mTotal) return;   // compaction early-exit
    extern __shared__ uint32_t skv[];
    uint32_t sb = smem_u32(skv);

    int tid = threadIdx.x;
    int wid = tid >> 5, lane = tid & 31;
    int warp_m = wid & 3, warp_n = wid >> 2;
    int lr = lane >> 2, lc = lane & 3;
    int n0 = (int)blockIdx.y * 64;

    int arow = tid >> 1, ahalf = tid & 1;
    const char* gA = (const char*)(A + (size_t)(m0 + arow) * K) + ahalf * 64;
    int brow = tid >> 2, bq = tid & 3;
    const char* gB = (const char*)(B + (size_t)(n0 + brow) * K) + bq * 32;
    uint32_t dA = sb + (uint32_t)(arow * KV_STRIDE + ahalf * 16) * 4;
    uint32_t dB = sb + (uint32_t)(128 * KV_STRIDE + brow * KV_STRIDE + bq * 8) * 4;

    float acc[2][4][4];
#pragma unroll
    for (int mt = 0; mt < 2; mt++)
#pragma unroll
        for (int nt = 0; nt < 4; nt++)
#pragma unroll
            for (int i = 0; i < 4; i++) acc[mt][nt][i] = 0.f;

#pragma unroll
    for (int st = 0; st < 2; st++) {
        uint32_t off = st * (KV_STAGE_U32 * 4);
        int kb = st * 128;
#pragma unroll
        for (int j = 0; j < 4; j++) CP16(dA + off + j * 16, gA + kb + j * 16);
#pragma unroll
        for (int j = 0; j < 2; j++) CP16(dB + off + j * 16, gB + kb + j * 16);
        CP_COMMIT();
    }

    for (int ch = 0; ch < CHUNKS; ch++) {
        CP_WAIT1();
        __syncthreads();
        const uint32_t* sA = skv + (ch & 1) * KV_STAGE_U32;
        const uint32_t* sBp = sA + 128 * KV_STRIDE;
#pragma unroll
        for (int ks = 0; ks < 4; ks++) {
            int kk = ks * 8;
            uint32_t af[2][4];
#pragma unroll
            for (int mt = 0; mt < 2; mt++) {
                int r = warp_m * 32 + mt * 16 + lr;
                int c = kk + lc;
                af[mt][0] = sA[r * KV_STRIDE + c];
                af[mt][1] = sA[(r + 8) * KV_STRIDE + c];
                af[mt][2] = sA[r * KV_STRIDE + c + 4];
                af[mt][3] = sA[(r + 8) * KV_STRIDE + c + 4];
            }
            uint32_t bf[4][2];
#pragma unroll
            for (int nt = 0; nt < 4; nt++) {
                int n = warp_n * 32 + nt * 8 + lr;
                bf[nt][0] = sBp[n * KV_STRIDE + kk + lc];
                bf[nt][1] = sBp[n * KV_STRIDE + kk + lc + 4];
            }
#pragma unroll
            for (int mt = 0; mt < 2; mt++)
#pragma unroll
                for (int nt = 0; nt < 4; nt++)
                    MMA_BF16(acc[mt][nt], af[mt], bf[nt]);
        }
        __syncthreads();
        if (ch < CHUNKS - 2) {
            uint32_t off = (ch & 1) * (KV_STAGE_U32 * 4);
            int kb = (ch + 2) * 128;
#pragma unroll
            for (int j = 0; j < 4; j++) CP16(dA + off + j * 16, gA + kb + j * 16);
#pragma unroll
            for (int j = 0; j < 2; j++) CP16(dB + off + j * 16, gB + kb + j * 16);
        }
        CP_COMMIT();
    }

#pragma unroll
    for (int mt = 0; mt < 2; mt++) {
        int r = m0 + warp_m * 32 + mt * 16 + lr;
#pragma unroll
        for (int nt = 0; nt < 4; nt++) {
            int cn = n0 + warp_n * 32 + nt * 8 + 2 * lc;
            float2 lo = make_float2(acc[mt][nt][0], acc[mt][nt][1]);
            float2 hi = make_float2(acc[mt][nt][2], acc[mt][nt][3]);
            if (EPI == 0) {
                float* dst = (n0 < 384) ? p0 : p1;
                int c = (n0 < 384) ? cn : cn - 384;
                *(float2*)&dst[(size_t)r * HDH + c] = lo;
                *(float2*)&dst[(size_t)(r + 8) * HDH + c] = hi;
            } else if (EPI == 1) {
                if (n0 < 384) {
                    *(float2*)&p0[(size_t)r * HDH + cn] = lo;
                    *(float2*)&p0[(size_t)(r + 8) * HDH + cn] = hi;
                } else {
                    int c = cn - 384;
                    float2 bb = *(const float2*)&q0[c];
                    lo.x += bb.x; lo.y += bb.y; hi.x += bb.x; hi.y += bb.y;
                    *(float2*)&p1[(size_t)r * HDH + c] = lo;
                    *(float2*)&p1[(size_t)(r + 8) * HDH + c] = hi;
                }
            } else {
                float2 bb = *(const float2*)&q1[cn];
                float2 n1 = *(const float2*)&q0[(size_t)r * DIM + cn];
                float2 n2 = *(const float2*)&q0[(size_t)(r + 8) * DIM + cn];
                lo.x += bb.x + n1.x; lo.y += bb.y + n1.y;
                hi.x += bb.x + n2.x; hi.y += bb.y + n2.y;
                *(float2*)&p0[(size_t)r * DIM + cn] = lo;
                *(float2*)&p0[(size_t)(r + 8) * DIM + cn] = hi;
            }
        }
    }
}

// ---------------- kernel 3: attention over compacted K/V ---------------------
// smem floats: [0,24576) 2 K|V stages; [24576,25088) sML. cAcc aliases stage0.
#define ATTN_SMEM_BYTES (25088 * 4)

__global__ void __launch_bounds__(256) attn_kernel()
{
    extern __shared__ float sm[];
    float* sML  = sm + 24576;
    float* cAcc = sm;

    int t = blockIdx.x >> 2;
    if (t >= g_numTiles) return;
    int hp = blockIdx.x & 3;
    int b = g_tile_b[t], n0 = g_tile_n0[t], nv = g_tile_nv[t];
    int off = g_off[b], cnt = g_cnt[b];
    int nCh = (cnt + 63) >> 6;
    int tid = threadIdx.x, w = tid >> 5, lane = tid & 31;
    int hl = w & 1, st = w >> 1;
    int h = hp * 2 + hl;

    float qv[48];
    if (lane < nv) {
        const float4* qp = (const float4*)&g_q[(n0 + lane) * HDH + h * D_HEAD];
#pragma unroll
        for (int i = 0; i < 12; i++) {
            float4 v = qp[i];
            qv[4 * i] = v.x; qv[4 * i + 1] = v.y; qv[4 * i + 2] = v.z; qv[4 * i + 3] = v.w;
        }
    } else {
#pragma unroll
        for (int i = 0; i < 48; i++) qv[i] = 0.f;
    }

    float m = -1e30f, l = 0.f;
    float acc[48];
#pragma unroll
    for (int i = 0; i < 48; i++) acc[i] = 0.f;

    uint32_t sb = smem_u32(sm);
    const char* Kg = (const char*)g_k;
    const char* Vg = (const char*)g_v;

    uint32_t so16[6];
    long     gOff[6];
#pragma unroll
    for (int q8 = 0; q8 < 6; q8++) {
        int idx = tid + q8 * 256;
        int row = idx / 24, c4 = idx % 24;
        so16[q8] = (uint32_t)(row * 24 + c4) * 16;
        gOff[q8] = ((long)(off + row) * 96 + hp * 24 + c4) * 16;
    }

#pragma unroll
    for (int cj = 0; cj < 2; cj++) {
        if (cj < nCh) {
            uint32_t kb = sb + (uint32_t)(cj * 12288) * 4;
            long chOff = (long)cj * 64 * 96 * 16;
#pragma unroll
            for (int q8 = 0; q8 < 6; q8++) {
                CP16(kb + so16[q8], Kg + gOff[q8] + chOff);
                CP16(kb + 6144 * 4 + so16[q8], Vg + gOff[q8] + chOff);
            }
        }
        CP_COMMIT();
    }

    for (int ci = 0; ci < nCh; ci++) {
        CP_WAIT1();
        __syncthreads();
        const float* sK = sm + (ci & 1) * 12288;
        const float* sV = sK + 6144;
        int rem = cnt - ci * 64;     // valid rows this chunk (>0)

        float sc16[16];
#pragma unroll 4
        for (int i = 0; i < 16; i++) {
            int s = 4 * i + st;
            if (s < rem) {
                const float4* kr = (const float4*)&sK[s * 96 + hl * 48];
                float d0 = 0.f, d1 = 0.f, d2 = 0.f, d3 = 0.f;
#pragma unroll
                for (int i4 = 0; i4 < 12; i4++) {
                    float4 kk = kr[i4];
                    d0 = fmaf(qv[4 * i4 + 0], kk.x, d0);
                    d1 = fmaf(qv[4 * i4 + 1], kk.y, d1);
                    d2 = fmaf(qv[4 * i4 + 2], kk.z, d2);
                    d3 = fmaf(qv[4 * i4 + 3], kk.w, d3);
                }
                sc16[i] = ((d0 + d1) + (d2 + d3)) * INV_SCALE;
            } else {
                sc16[i] = -1e30f;
            }
        }
        float mc = -1e30f;
#pragma unroll
        for (int i = 0; i < 16; i++) mc = fmaxf(mc, sc16[i]);
        if (mc > -1e29f) {
            float mn = fmaxf(m, mc);
            float f = __expf(m - mn);
            l *= f;
#pragma unroll
            for (int d = 0; d < 48; d++) acc[d] *= f;
            m = mn;
#pragma unroll 2
            for (int i = 0; i < 16; i++) {
                if (sc16[i] > -1e29f) {
                    float p = __expf(sc16[i] - m);
                    l += p;
                    const float4* vr = (const float4*)&sV[(4 * i + st) * 96 + hl * 48];
#pragma unroll
                    for (int i4 = 0; i4 < 12; i4++) {
                        float4 vv = vr[i4];
                        acc[4 * i4 + 0] = fmaf(p, vv.x, acc[4 * i4 + 0]);
                        acc[4 * i4 + 1] = fmaf(p, vv.y, acc[4 * i4 + 1]);
                        acc[4 * i4 + 2] = fmaf(p, vv.z, acc[4 * i4 + 2]);
                        acc[4 * i4 + 3] = fmaf(p, vv.w, acc[4 * i4 + 3]);
                    }
                }
            }
        }
        __syncthreads();
        if (ci + 2 < nCh) {
            int cj = ci + 2;
            uint32_t kb = sb + (uint32_t)((cj & 1) * 12288) * 4;
            long chOff = (long)cj * 64 * 96 * 16;
#pragma unroll
            for (int q8 = 0; q8 < 6; q8++) {
                CP16(kb + so16[q8], Kg + gOff[q8] + chOff);
                CP16(kb + 6144 * 4 + so16[q8], Vg + gOff[q8] + chOff);
            }
        }
        CP_COMMIT();
    }
    CP_WAIT0();
    __syncthreads();

    {
        int r = (st * 32 + lane) * 2 + hl;
        sML[r * 2 + 0] = m;
        sML[r * 2 + 1] = l;
#pragma unroll
        for (int d = 0; d < 48; d++) cAcc[r * 48 + d] = acc[d];
    }
    __syncthreads();

    if (tid < 64) {
        int j = tid >> 1, hlf = tid & 1;
        int hf = hp * 2 + hlf;
        float M = -1e30f;
#pragma unroll
        for (int s = 0; s < 4; s++)
            M = fmaxf(M, sML[((s * 32 + j) * 2 + hlf) * 2]);
        float L = 0.f, e[4];
#pragma unroll
        for (int s = 0; s < 4; s++) {
            float ms = sML[((s * 32 + j) * 2 + hlf) * 2];
            float ls = sML[((s * 32 + j) * 2 + hlf) * 2 + 1];
            e[s] = __expf(ms - M);
            L += ls * e[s];
        }
        float invL = 1.f / (L + 1e-9f);
        if (j < nv) {
            float* outp = &g_feat[(n0 + j) * HDH + hf * D_HEAD];
            for (int d = 0; d < 48; d++) {
                float F = 0.f;
#pragma unroll
                for (int s = 0; s < 4; s++)
                    F += cAcc[((s * 32 + j) * 2 + hlf) * 48 + d] * e[s];
                outp[d] = F * invL;
            }
        }
    }
}

// ---------------- launch -----------------------------------------------------
extern "C" void kernel_launch(void* const* d_in, const int* in_sizes, int n_in,
                              void* d_out, int out_size) {
    const float* node  = (const float*)d_in[0];
    const float* emb   = (const float*)d_in[1];
    const int*   mask  = (const int*)d_in[2];
    const void*  batch = d_in[3];
    const float* ln_g  = (const float*)d_in[4];
    const float* ln_b  = (const float*)d_in[5];
    const float* Wq    = (const float*)d_in[6];
    const float* Wk    = (const float*)d_in[7];
    const float* Wv    = (const float*)d_in[8];
    const float* Wg    = (const float*)d_in[9];
    const float* bg    = (const float*)d_in[10];
    const float* Wback = (const float*)d_in[11];
    const float* bback = (const float*)d_in[12];
    float* out = (float*)d_out;

    float *p_q, *p_gpre, *p_k, *p_v;
    bf16 *p_y, *p_gf, *p_wt, *p_wqg, *p_wbt, *p_embt;
    cudaGetSymbolAddress((void**)&p_q,    g_q);
    cudaGetSymbolAddress((void**)&p_gpre, g_gpre);
    cudaGetSymbolAddress((void**)&p_k,    g_k);
    cudaGetSymbolAddress((void**)&p_v,    g_v);
    cudaGetSymbolAddress((void**)&p_y,    g_y);
    cudaGetSymbolAddress((void**)&p_gf,   g_gf);
    cudaGetSymbolAddress((void**)&p_wt,   g_wt);
    cudaGetSymbolAddress((void**)&p_wqg,  g_wqg);
    cudaGetSymbolAddress((void**)&p_wbt,  g_wbt);
    cudaGetSymbolAddress((void**)&p_embt, g_embt);

    cudaFuncSetAttribute(attn_kernel,
                         cudaFuncAttributeMaxDynamicSharedMemorySize, ATTN_SMEM_BYTES);
    cudaFuncSetAttribute(gemm_bf16<4, 1>,
                         cudaFuncAttributeMaxDynamicSharedMemorySize, KV_SMEM_BYTES);
    cudaFuncSetAttribute(gemm_bf16<20, 0>,
                         cudaFuncAttributeMaxDynamicSharedMemorySize, KV_SMEM_BYTES);
    cudaFuncSetAttribute(gemm_bf16<6, 2>,
                         cudaFuncAttributeMaxDynamicSharedMemorySize, KV_SMEM_BYTES);

    setup_kernel<<<1, 256>>>(batch, mask);
    cvt_kernel<<<8192, 160>>>(emb);
    transpose_bf16<<<dim3(DIM / 32, HDH / 32), 256>>>(Wq, DIM, HDH, p_wqg, 0);
    transpose_bf16<<<dim3(DIM / 32, HDH / 32), 256>>>(Wg, DIM, HDH, p_wqg, 384);
    transpose_bf16<<<dim3(D_SEQ / 32, HDH / 32), 256>>>(Wk, D_SEQ, HDH, p_wt, 0);
    transpose_bf16<<<dim3(D_SEQ / 32, HDH / 32), 256>>>(Wv, D_SEQ, HDH, p_wt, 384);
    transpose_bf16<<<dim3(HDH / 32, DIM / 32), 256>>>(Wback, HDH, DIM, p_wbt, 0);
    ln_kernel<<<N_NODE / 8, 256>>>(node, ln_g, ln_b);
    gemm_bf16<4, 1><<<dim3(16, 12), 256, KV_SMEM_BYTES>>>(
        p_y, p_wqg, p_q, p_gpre, bg, nullptr);
    gemm_bf16<20, 0><<<dim3(64, 12), 256, KV_SMEM_BYTES>>>(
        p_embt, p_wt, p_k, p_v, nullptr, nullptr);
    attn_kernel<<<288, 256, ATTN_SMEM_BYTES>>>();
    gf_kernel<<<N_NODE * HDH / (8 * 256), 256>>>();
    gemm_bf16<6, 2><<<dim3(16, 4), 256, KV_SMEM_BYTES>>>(
        p_gf, p_wbt, out, nullptr, node, bback);
}

// round 17
// speedup vs baseline: 1.9871x; 1.5378x over previous
#include <cuda_runtime.h>
#include <cuda_bf16.h>
#include <cstdint>

#define N_NODE 2048
#define DIM 256
#define D_SEQ 1280
#define HDH 384
#define N_HEAD 8
#define D_HEAD 48
#define B_GRAPH 8
#define S_LEN 1024
#define INV_SCALE 0.14433756729740643f
#define VT_PITCH 8256

typedef __nv_bfloat16 bf16;

// ---------------- scratch ----------------------------------------------------
__device__ __align__(128) bf16  g_kb[(8192 + 64) * HDH];      // compacted K bf16 [s][d]
__device__ __align__(128) bf16  g_vt[HDH * VT_PITCH];         // compacted V^T bf16 [d][s]
__device__ __align__(128) bf16  g_qb[(N_NODE + 32) * HDH];    // bf16 q * INV_SCALE
__device__ __align__(128) float g_gpre[N_NODE * HDH];
__device__ __align__(128) float g_feat[N_NODE * HDH];
__device__ __align__(128) bf16  g_y[N_NODE * DIM];
__device__ __align__(128) bf16  g_gf[N_NODE * HDH];
__device__ __align__(128) bf16  g_wt[768 * D_SEQ];
__device__ __align__(128) bf16  g_wqg[768 * DIM];
__device__ __align__(128) bf16  g_wbt[DIM * HDH];
__device__ __align__(128) bf16  g_embt[8192 * D_SEQ];
__device__ int g_pos[8192];
__device__ int g_off[B_GRAPH];
__device__ int g_cnt[B_GRAPH];
__device__ int g_mTotal;
__device__ int g_numTiles;
__device__ int g_tile_b[80];
__device__ int g_tile_n0[80];
__device__ int g_tile_nv[80];

__device__ __forceinline__ uint32_t smem_u32(const void* p) {
    uint32_t a;
    asm("{ .reg .u64 t; cvta.to.shared.u64 t, %1; cvt.u32.u64 %0, t; }"
        : "=r"(a) : "l"(p));
    return a;
}
__device__ __forceinline__ uint32_t pack_bf16x2(float lo, float hi) {
    uint32_t d;
    asm("cvt.rn.bf16x2.f32 %0, %1, %2;" : "=r"(d) : "f"(hi), "f"(lo));
    return d;
}
#define CP16(dst, src) \
    asm volatile("cp.async.cg.shared.global [%0], [%1], 16;" \
                 :: "r"(dst), "l"(src) : "memory")
#define CP_COMMIT() asm volatile("cp.async.commit_group;" ::: "memory")
#define CP_WAIT1()  asm volatile("cp.async.wait_group 1;" ::: "memory")
#define CP_WAIT0()  asm volatile("cp.async.wait_group 0;" ::: "memory")

#define MMA_BF16(c, a, b) \
    asm volatile("mma.sync.aligned.m16n8k16.row.col.f32.bf16.bf16.f32 " \
        "{%0,%1,%2,%3}, {%4,%5,%6,%7}, {%8,%9}, {%0,%1,%2,%3};" \
        : "+f"((c)[0]), "+f"((c)[1]), "+f"((c)[2]), "+f"((c)[3]) \
        : "r"((a)[0]), "r"((a)[1]), "r"((a)[2]), "r"((a)[3]), \
          "r"((b)[0]), "r"((b)[1]))

// ---------------- kernel 0: batch tiles + mask compaction (64-padded) --------
__global__ void setup_kernel(const void* batch_raw, const int* __restrict__ mask) {
    __shared__ int cnt[8];
    __shared__ int mcnt[8], moff[8];
    __shared__ int ok32;
    int tid = threadIdx.x, w = tid >> 5, lane = tid & 31;
    if (tid < 8) cnt[tid] = 0;
    if (tid == 0) ok32 = 1;
    __syncthreads();
    const int* b32 = (const int*)batch_raw;
    int bad = 0;
    for (int i = tid; i < N_NODE; i += 256) {
        int v = b32[i];
        if (v < 0 || v >= 8) bad = 1;
        if (i + 1 < N_NODE && b32[i + 1] < v) bad = 1;
    }
    if (bad) ok32 = 0;
    __syncthreads();
    const long long* b64 = (const long long*)batch_raw;
    for (int i = tid; i < N_NODE; i += 256) {
        int v = ok32 ? b32[i] : (int)b64[i];
        v = min(max(v, 0), 7);
        atomicAdd(&cnt[v], 1);
    }
    {
        int c = 0;
        for (int g = 0; g < 32; g++) {
            int v = mask[w * S_LEN + g * 32 + lane] != 0;
            c += __popc(__ballot_sync(0xffffffffu, v));
        }
        if (lane == 0) mcnt[w] = c;
    }
    __syncthreads();
    if (tid == 0) {
        int off = 0, t = 0;
        for (int b = 0; b < 8; b++) {
            int nb = cnt[b];
            for (int s = 0; s < nb; s += 32) {
                g_tile_b[t] = b;
                g_tile_n0[t] = off + s;
                g_tile_nv[t] = min(32, nb - s);
                t++;
            }
            off += nb;
        }
        g_numTiles = t;
        int o = 0;
        for (int b = 0; b < 8; b++) {
            moff[b] = o; g_off[b] = o; g_cnt[b] = mcnt[b];
            o += (mcnt[b] + 63) & ~63;       // pad to 64 (alignment + zero gaps)
        }
        g_mTotal = o;
    }
    __syncthreads();
    {
        int o = moff[w];
        for (int g = 0; g < 32; g++) {
            int idx = w * S_LEN + g * 32 + lane;
            int v = mask[idx] != 0;
            uint32_t bal = __ballot_sync(0xffffffffu, v);
            g_pos[idx] = v ? (o + __popc(bal & ((1u << lane) - 1))) : -1;
            o += __popc(bal);
        }
    }
}

// ---------------- kernel 0a: compacted emb -> bf16 ---------------------------
__global__ void __launch_bounds__(160) cvt_kernel(const float* __restrict__ emb) {
    int r = blockIdx.x;
    int p = g_pos[r];
    if (p < 0) return;
    int t = threadIdx.x;
    const float4* src = (const float4*)(emb + (size_t)r * D_SEQ);
    float4 v0 = src[2 * t], v1 = src[2 * t + 1];
    bf16 o[8];
    o[0] = __float2bfloat16_rn(v0.x); o[1] = __float2bfloat16_rn(v0.y);
    o[2] = __float2bfloat16_rn(v0.z); o[3] = __float2bfloat16_rn(v0.w);
    o[4] = __float2bfloat16_rn(v1.x); o[5] = __float2bfloat16_rn(v1.y);
    o[6] = __float2bfloat16_rn(v1.z); o[7] = __float2bfloat16_rn(v1.w);
    ((uint4*)(g_embt + (size_t)p * D_SEQ))[t] = *(uint4*)o;
}

// ------------ kernel 0b: transpose + bf16 ------------------------------------
__global__ void __launch_bounds__(256) transpose_bf16(
    const float* __restrict__ src, int R, int C,
    bf16* __restrict__ dst, int rowOff)
{
    __shared__ float tile[32][33];
    int kb = blockIdx.x * 32, nb = blockIdx.y * 32;
    int tx = threadIdx.x & 31, ty = threadIdx.x >> 5;
#pragma unroll
    for (int i = 0; i < 4; i++)
        tile[ty + i * 8][tx] = src[(size_t)(kb + ty + i * 8) * C + nb + tx];
    __syncthreads();
#pragma unroll
    for (int i = 0; i < 4; i++)
        dst[(size_t)(rowOff + nb + ty + i * 8) * R + kb + tx] =
            __float2bfloat16_rn(tile[tx][ty + i * 8]);
}

// ---------------- kernel 1: layernorm -> g_y (bf16) --------------------------
__global__ void __launch_bounds__(256) ln_kernel(
    const float* __restrict__ node,
    const float* __restrict__ ln_g, const float* __restrict__ ln_b)
{
    int w = threadIdx.x >> 5, lane = threadIdx.x & 31;
    int n = blockIdx.x * 8 + w;
    float xv[8];
    float sx = 0.f, sxx = 0.f;
#pragma unroll
    for (int i = 0; i < 8; i++) {
        float x = node[n * DIM + lane + i * 32];
        xv[i] = x; sx += x; sxx += x * x;
    }
#pragma unroll
    for (int o = 16; o > 0; o >>= 1) {
        sx  += __shfl_xor_sync(0xffffffffu, sx, o);
        sxx += __shfl_xor_sync(0xffffffffu, sxx, o);
    }
    float mu = sx * (1.f / DIM);
    float var = sxx * (1.f / DIM) - mu * mu;
    float inv = rsqrtf(var + 1e-5f);
#pragma unroll
    for (int i = 0; i < 8; i++) {
        int d = lane + i * 32;
        g_y[n * DIM + d] =
            __float2bfloat16_rn((xv[i] - mu) * inv * ln_g[d] + ln_b[d]);
    }
}

// ---------------- kernel 1b: gate*feat -> g_gf (bf16) ------------------------
__global__ void __launch_bounds__(256) gf_kernel() {
    int i = blockIdx.x * 256 + threadIdx.x;
    float4 g0 = ((const float4*)g_gpre)[2 * i];
    float4 g1 = ((const float4*)g_gpre)[2 * i + 1];
    float4 f0 = ((const float4*)g_feat)[2 * i];
    float4 f1 = ((const float4*)g_feat)[2 * i + 1];
    bf16 o[8];
    o[0] = __float2bfloat16_rn(f0.x / (1.f + __expf(-g0.x)));
    o[1] = __float2bfloat16_rn(f0.y / (1.f + __expf(-g0.y)));
    o[2] = __float2bfloat16_rn(f0.z / (1.f + __expf(-g0.z)));
    o[3] = __float2bfloat16_rn(f0.w / (1.f + __expf(-g0.w)));
    o[4] = __float2bfloat16_rn(f1.x / (1.f + __expf(-g1.x)));
    o[5] = __float2bfloat16_rn(f1.y / (1.f + __expf(-g1.y)));
    o[6] = __float2bfloat16_rn(f1.z / (1.f + __expf(-g1.z)));
    o[7] = __float2bfloat16_rn(f1.w / (1.f + __expf(-g1.w)));
    ((uint4*)g_gf)[i] = *(uint4*)o;
}

// ---------------- unified BF16 mma.sync GEMM ---------------------------------
#define KV_STRIDE 36
#define KV_STAGE_U32 ((128 + 64) * KV_STRIDE)
#define KV_SMEM_BYTES (2 * KV_STAGE_U32 * 4)

// EPI 0: n<384 -> K bf16 [s][384]; n>=384 -> V^T bf16 [d][VT_PITCH]
// EPI 1: n<384 -> q bf16*INV_SCALE [node][384]; n>=384 -> gpre fp32 (+bg)
// EPI 2: out fp32 = node + acc + bback
template<int CHUNKS, int EPI>
__global__ void __launch_bounds__(256, 4) gemm_bf16(
    const bf16* __restrict__ A, const bf16* __restrict__ B,
    void* __restrict__ p0, void* __restrict__ p1,
    const float* __restrict__ q0, const float* __restrict__ q1)
{
    const int K = CHUNKS * 64;
    int m0 = (int)blockIdx.x * 128;
    if (EPI == 0 && m0 >= g_mTotal) return;
    extern __shared__ uint32_t skv[];
    uint32_t sb = smem_u32(skv);

    int tid = threadIdx.x;
    int wid = tid >> 5, lane = tid & 31;
    int warp_m = wid & 3, warp_n = wid >> 2;
    int lr = lane >> 2, lc = lane & 3;
    int n0 = (int)blockIdx.y * 64;

    int arow = tid >> 1, ahalf = tid & 1;
    const char* gA = (const char*)(A + (size_t)(m0 + arow) * K) + ahalf * 64;
    int brow = tid >> 2, bq = tid & 3;
    const char* gB = (const char*)(B + (size_t)(n0 + brow) * K) + bq * 32;
    uint32_t dA = sb + (uint32_t)(arow * KV_STRIDE + ahalf * 16) * 4;
    uint32_t dB = sb + (uint32_t)(128 * KV_STRIDE + brow * KV_STRIDE + bq * 8) * 4;

    float acc[2][4][4];
#pragma unroll
    for (int mt = 0; mt < 2; mt++)
#pragma unroll
        for (int nt = 0; nt < 4; nt++)
#pragma unroll
            for (int i = 0; i < 4; i++) acc[mt][nt][i] = 0.f;

#pragma unroll
    for (int st = 0; st < 2; st++) {
        uint32_t off = st * (KV_STAGE_U32 * 4);
        int kb = st * 128;
#pragma unroll
        for (int j = 0; j < 4; j++) CP16(dA + off + j * 16, gA + kb + j * 16);
#pragma unroll
        for (int j = 0; j < 2; j++) CP16(dB + off + j * 16, gB + kb + j * 16);
        CP_COMMIT();
    }

    for (int ch = 0; ch < CHUNKS; ch++) {
        CP_WAIT1();
        __syncthreads();
        const uint32_t* sA = skv + (ch & 1) * KV_STAGE_U32;
        const uint32_t* sBp = sA + 128 * KV_STRIDE;
#pragma unroll
        for (int ks = 0; ks < 4; ks++) {
            int kk = ks * 8;
            uint32_t af[2][4];
#pragma unroll
            for (int mt = 0; mt < 2; mt++) {
                int r = warp_m * 32 + mt * 16 + lr;
                int c = kk + lc;
                af[mt][0] = sA[r * KV_STRIDE + c];
                af[mt][1] = sA[(r + 8) * KV_STRIDE + c];
                af[mt][2] = sA[r * KV_STRIDE + c + 4];
                af[mt][3] = sA[(r + 8) * KV_STRIDE + c + 4];
            }
            uint32_t bf[4][2];
#pragma unroll
            for (int nt = 0; nt < 4; nt++) {
                int n = warp_n * 32 + nt * 8 + lr;
                bf[nt][0] = sBp[n * KV_STRIDE + kk + lc];
                bf[nt][1] = sBp[n * KV_STRIDE + kk + lc + 4];
            }
#pragma unroll
            for (int mt = 0; mt < 2; mt++)
#pragma unroll
                for (int nt = 0; nt < 4; nt++)
                    MMA_BF16(acc[mt][nt], af[mt], bf[nt]);
        }
        __syncthreads();
        if (ch < CHUNKS - 2) {
            uint32_t off = (ch & 1) * (KV_STAGE_U32 * 4);
            int kb = (ch + 2) * 128;
#pragma unroll
            for (int j = 0; j < 4; j++) CP16(dA + off + j * 16, gA + kb + j * 16);
#pragma unroll
            for (int j = 0; j < 2; j++) CP16(dB + off + j * 16, gB + kb + j * 16);
        }
        CP_COMMIT();
    }

#pragma unroll
    for (int mt = 0; mt < 2; mt++) {
        int r = m0 + warp_m * 32 + mt * 16 + lr;
#pragma unroll
        for (int nt = 0; nt < 4; nt++) {
            int cn = n0 + warp_n * 32 + nt * 8 + 2 * lc;
            float2 lo = make_float2(acc[mt][nt][0], acc[mt][nt][1]);
            float2 hi = make_float2(acc[mt][nt][2], acc[mt][nt][3]);
            if (EPI == 0) {
                if (n0 < 384) {
                    bf16* kb = (bf16*)p0;
                    *(uint32_t*)&kb[(size_t)r * HDH + cn] = pack_bf16x2(lo.x, lo.y);
                    *(uint32_t*)&kb[(size_t)(r + 8) * HDH + cn] = pack_bf16x2(hi.x, hi.y);
                } else {
                    bf16* vt = (bf16*)p1;
                    int d = cn - 384;
                    vt[(size_t)d * VT_PITCH + r] = __float2bfloat16_rn(lo.x);
                    vt[(size_t)(d + 1) * VT_PITCH + r] = __float2bfloat16_rn(lo.y);
                    vt[(size_t)d * VT_PITCH + r + 8] = __float2bfloat16_rn(hi.x);
                    vt[(size_t)(d + 1) * VT_PITCH + r + 8] = __float2bfloat16_rn(hi.y);
                }
            } else if (EPI == 1) {
                if (n0 < 384) {
                    bf16* qb = (bf16*)p0;
                    *(uint32_t*)&qb[(size_t)r * HDH + cn] =
                        pack_bf16x2(lo.x * INV_SCALE, lo.y * INV_SCALE);
                    *(uint32_t*)&qb[(size_t)(r + 8) * HDH + cn] =
                        pack_bf16x2(hi.x * INV_SCALE, hi.y * INV_SCALE);
                } else {
                    float* gp = (float*)p1;
                    int c = cn - 384;
                    float2 bb = *(const float2*)&q0[c];
                    lo.x += bb.x; lo.y += bb.y; hi.x += bb.x; hi.y += bb.y;
                    *(float2*)&gp[(size_t)r * HDH + c] = lo;
                    *(float2*)&gp[(size_t)(r + 8) * HDH + c] = hi;
                }
            } else {
                float* op = (float*)p0;
                float2 bb = *(const float2*)&q1[cn];
                float2 n1 = *(const float2*)&q0[(size_t)r * DIM + cn];
                float2 n2 = *(const float2*)&q0[(size_t)(r + 8) * DIM + cn];
                lo.x += bb.x + n1.x; lo.y += bb.y + n1.y;
                hi.x += bb.x + n2.x; hi.y += bb.y + n2.y;
                *(float2*)&op[(size_t)r * DIM + cn] = lo;
                *(float2*)&op[(size_t)(r + 8) * DIM + cn] = hi;
            }
        }
    }
}

// ---------------- kernel 3: tensor-core flash attention ----------------------
// block = (32-node tile, head pair). warp = (head hl, 16-s stripe st).
// smem u32 layout per stage: K [2 heads][64 s][28], V^T [2 heads][48 d][36].
#define AT_KSTR 28
#define AT_VSTR 36
#define AT_KHEAD (64 * AT_KSTR)
#define AT_VHEAD (48 * AT_VSTR)
#define AT_VBASE (2 * AT_KHEAD)
#define AT_STAGE (AT_VBASE + 2 * AT_VHEAD)     // 7040 u32
#define AT_SMLOFF (2 * AT_STAGE)               // 14080
#define ATTN_SMEM_BYTES ((AT_SMLOFF + 512) * 4)

__global__ void __launch_bounds__(256, 2) attn_kernel()
{
    extern __shared__ uint32_t su[];
    float* sML  = (float*)(su + AT_SMLOFF);
    float* cAcc = (float*)su;                 // alias stages (post-loop)

    int t = blockIdx.x >> 2;
    if (t >= g_numTiles) return;
    int hp = blockIdx.x & 3;
    int b = g_tile_b[t], n0 = g_tile_n0[t], nv = g_tile_nv[t];
    int off = g_off[b], cnt = g_cnt[b];
    int nCh = (cnt + 63) >> 6;
    int tid = threadIdx.x, w = tid >> 5, lane = tid & 31;
    int hl = w & 1, st = w >> 1;
    int lr = lane >> 2, lc = lane & 3;
    uint32_t sb = smem_u32(su);

    // Q A-fragments: [mt][ks][4], q pre-scaled bf16, direct global u32 loads
    uint32_t aQ[2][3][4];
#pragma unroll
    for (int mt = 0; mt < 2; mt++)
#pragma unroll
        for (int ks = 0; ks < 3; ks++) {
            size_t base = (size_t)(n0 + mt * 16 + lr) * HDH + hp * 96 + hl * 48
                          + ks * 16 + 2 * lc;
            aQ[mt][ks][0] = *(const uint32_t*)&g_qb[base];
            aQ[mt][ks][1] = *(const uint32_t*)&g_qb[base + 8 * HDH];
            aQ[mt][ks][2] = *(const uint32_t*)&g_qb[base + 8];
            aQ[mt][ks][3] = *(const uint32_t*)&g_qb[base + 8 * HDH + 8];
        }

    // staging slots: 6 cp16/thread (K: idx<768, V: idx>=768)
    uint32_t sdst[6];
    const char* ssrc0[6];
    int sstr[6];
#pragma unroll
    for (int j = 0; j < 6; j++) {
        int idx = tid + j * 256;
        if (idx < 768) {
            int kh = idx / 384, r6 = idx % 384, rr = r6 / 6, c = r6 % 6;
            sdst[j] = (uint32_t)(kh * AT_KHEAD + rr * AT_KSTR + c * 4);
            ssrc0[j] = (const char*)g_kb +
                ((size_t)(off + rr) * HDH + hp * 96 + kh * 48 + c * 8) * 2;
            sstr[j] = 64 * HDH * 2;
        } else {
            int v = idx - 768;
            int vh = v / 384, r8 = v % 384, rr = r8 / 8, c = r8 % 8;
            sdst[j] = (uint32_t)(AT_VBASE + vh * AT_VHEAD + rr * AT_VSTR + c * 4);
            ssrc0[j] = (const char*)g_vt +
                ((size_t)(hp * 96 + vh * 48 + rr) * VT_PITCH + off + c * 8) * 2;
            sstr[j] = 64 * 2;
        }
    }

    float acc[2][6][4];
#pragma unroll
    for (int mt = 0; mt < 2; mt++)
#pragma unroll
        for (int nt = 0; nt < 6; nt++)
#pragma unroll
            for (int i = 0; i < 4; i++) acc[mt][nt][i] = 0.f;
    float mreg[4] = {-1e30f, -1e30f, -1e30f, -1e30f};
    float lreg[4] = {0.f, 0.f, 0.f, 0.f};

#pragma unroll
    for (int cj = 0; cj < 2; cj++) {
        if (cj < nCh) {
            uint32_t stg = sb + (uint32_t)(cj * AT_STAGE) * 4;
#pragma unroll
            for (int j = 0; j < 6; j++)
                CP16(stg + sdst[j] * 4, ssrc0[j] + (size_t)cj * sstr[j]);
        }
        CP_COMMIT();
    }

    for (int ci = 0; ci < nCh; ci++) {
        CP_WAIT1();
        __syncthreads();
        const uint32_t* S = su + (ci & 1) * AT_STAGE;
        int rem = cnt - ci * 64;

        // QK^T
        float sc[2][2][4];
#pragma unroll
        for (int mt = 0; mt < 2; mt++)
#pragma unroll
            for (int nt = 0; nt < 2; nt++)
#pragma unroll
                for (int i = 0; i < 4; i++) sc[mt][nt][i] = 0.f;
#pragma unroll
        for (int ks = 0; ks < 3; ks++) {
            uint32_t bk[2][2];
#pragma unroll
            for (int nt = 0; nt < 2; nt++) {
                int r = hl * AT_KHEAD + (st * 16 + nt * 8 + lr) * AT_KSTR + ks * 8 + lc;
                bk[nt][0] = S[r];
                bk[nt][1] = S[r + 4];
            }
#pragma unroll
            for (int mt = 0; mt < 2; mt++)
#pragma unroll
                for (int nt = 0; nt < 2; nt++)
                    MMA_BF16(sc[mt][nt], aQ[mt][ks], bk[nt]);
        }
        // tail mask
#pragma unroll
        for (int nt = 0; nt < 2; nt++) {
            int c0 = st * 16 + nt * 8 + 2 * lc;
            if (c0 >= rem) {
                sc[0][nt][0] = sc[0][nt][2] = -1e30f;
                sc[1][nt][0] = sc[1][nt][2] = -1e30f;
            }
            if (c0 + 1 >= rem) {
                sc[0][nt][1] = sc[0][nt][3] = -1e30f;
                sc[1][nt][1] = sc[1][nt][3] = -1e30f;
            }
        }
        // online softmax per row; pack P into A-fragments
        uint32_t pa[2][4];
#pragma unroll
        for (int mt = 0; mt < 2; mt++)
#pragma unroll
            for (int rh = 0; rh < 2; rh++) {
                float v0 = sc[mt][0][2 * rh],     v1 = sc[mt][0][2 * rh + 1];
                float v2 = sc[mt][1][2 * rh],     v3 = sc[mt][1][2 * rh + 1];
                float rmax = fmaxf(fmaxf(v0, v1), fmaxf(v2, v3));
                rmax = fmaxf(rmax, __shfl_xor_sync(0xffffffffu, rmax, 1));
                rmax = fmaxf(rmax, __shfl_xor_sync(0xffffffffu, rmax, 2));
                int mi = 2 * mt + rh;
                float mn = fmaxf(mreg[mi], rmax);
                float f = __expf(mreg[mi] - mn);
                mreg[mi] = mn;
                lreg[mi] *= f;
#pragma unroll
                for (int nt = 0; nt < 6; nt++) {
                    acc[mt][nt][2 * rh] *= f;
                    acc[mt][nt][2 * rh + 1] *= f;
                }
                float p0 = (v0 > -1e29f) ? __expf(v0 - mn) : 0.f;
                float p1 = (v1 > -1e29f) ? __expf(v1 - mn) : 0.f;
                float p2 = (v2 > -1e29f) ? __expf(v2 - mn) : 0.f;
                float p3 = (v3 > -1e29f) ? __expf(v3 - mn) : 0.f;
                float rs = (p0 + p1) + (p2 + p3);
                rs += __shfl_xor_sync(0xffffffffu, rs, 1);
                rs += __shfl_xor_sync(0xffffffffu, rs, 2);
                lreg[mi] += rs;
                pa[mt][rh]     = pack_bf16x2(p0, p1);   // a0/a1: nt0 rows lr,lr+8
                pa[mt][2 + rh] = pack_bf16x2(p2, p3);   // a2/a3: nt1
            }
        // P @ V
#pragma unroll
        for (int nt = 0; nt < 6; nt++) {
            int r = AT_VBASE + hl * AT_VHEAD + (nt * 8 + lr) * AT_VSTR + st * 8 + lc;
            uint32_t bv[2];
            bv[0] = S[r];
            bv[1] = S[r + 4];
#pragma unroll
            for (int mt = 0; mt < 2; mt++)
                MMA_BF16(acc[mt][nt], pa[mt], bv);
        }
        __syncthreads();
        if (ci + 2 < nCh) {
            uint32_t stg = sb + (uint32_t)((ci & 1) * AT_STAGE) * 4;
            size_t co = (size_t)(ci + 2);
#pragma unroll
            for (int j = 0; j < 6; j++)
                CP16(stg + sdst[j] * 4, ssrc0[j] + co * sstr[j]);
        }
        CP_COMMIT();
    }
    CP_WAIT0();
    __syncthreads();

    // publish per-stripe partials
#pragma unroll
    for (int mt = 0; mt < 2; mt++)
#pragma unroll
        for (int rh = 0; rh < 2; rh++) {
            int node = mt * 16 + rh * 8 + lr;
            int r = (st * 32 + node) * 2 + hl;
            if (lc == 0) {
                sML[r * 2 + 0] = mreg[2 * mt + rh];
                sML[r * 2 + 1] = lreg[2 * mt + rh];
            }
#pragma unroll
            for (int nt = 0; nt < 6; nt++)
                *(float2*)&cAcc[r * 48 + nt * 8 + 2 * lc] =
                    make_float2(acc[mt][nt][2 * rh], acc[mt][nt][2 * rh + 1]);
        }
    __syncthreads();

    // merge 4 stripes per (node, head)
    if (tid < 64) {
        int j = tid >> 1, hlf = tid & 1;
        int hf = hp * 2 + hlf;
        float M = -1e30f;
#pragma unroll
        for (int s = 0; s < 4; s++)
            M = fmaxf(M, sML[((s * 32 + j) * 2 + hlf) * 2]);
        float L = 0.f, e[4];
#pragma unroll
        for (int s = 0; s < 4; s++) {
            float ms = sML[((s * 32 + j) * 2 + hlf) * 2];
            float ls = sML[((s * 32 + j) * 2 + hlf) * 2 + 1];
            e[s] = __expf(ms - M);
            L += ls * e[s];
        }
        float invL = 1.f / (L + 1e-9f);
        if (j < nv) {
            float* outp = &g_feat[(n0 + j) * HDH + hf * D_HEAD];
            for (int d = 0; d < 48; d++) {
                float F = 0.f;
#pragma unroll
                for (int s = 0; s < 4; s++)
                    F += cAcc[((s * 32 + j) * 2 + hlf) * 48 + d] * e[s];
                outp[d] = F * invL;
            }
        }
    }
}

// ---------------- launch -----------------------------------------------------
extern "C" void kernel_launch(void* const* d_in, const int* in_sizes, int n_in,
                              void* d_out, int out_size) {
    const float* node  = (const float*)d_in[0];
    const float* emb   = (const float*)d_in[1];
    const int*   mask  = (const int*)d_in[2];
    const void*  batch = d_in[3];
    const float* ln_g  = (const float*)d_in[4];
    const float* ln_b  = (const float*)d_in[5];
    const float* Wq    = (const float*)d_in[6];
    const float* Wk    = (const float*)d_in[7];
    const float* Wv    = (const float*)d_in[8];
    const float* Wg    = (const float*)d_in[9];
    const float* bg    = (const float*)d_in[10];
    const float* Wback = (const float*)d_in[11];
    const float* bback = (const float*)d_in[12];
    float* out = (float*)d_out;

    float *p_gpre;
    bf16 *p_y, *p_gf, *p_wt, *p_wqg, *p_wbt, *p_embt, *p_kb, *p_vt, *p_qb;
    cudaGetSymbolAddress((void**)&p_gpre, g_gpre);
    cudaGetSymbolAddress((void**)&p_kb,   g_kb);
    cudaGetSymbolAddress((void**)&p_vt,   g_vt);
    cudaGetSymbolAddress((void**)&p_qb,   g_qb);
    cudaGetSymbolAddress((void**)&p_y,    g_y);
    cudaGetSymbolAddress((void**)&p_gf,   g_gf);
    cudaGetSymbolAddress((void**)&p_wt,   g_wt);
    cudaGetSymbolAddress((void**)&p_wqg,  g_wqg);
    cudaGetSymbolAddress((void**)&p_wbt,  g_wbt);
    cudaGetSymbolAddress((void**)&p_embt, g_embt);

    cudaFuncSetAttribute(attn_kernel,
                         cudaFuncAttributeMaxDynamicSharedMemorySize, ATTN_SMEM_BYTES);
    cudaFuncSetAttribute(gemm_bf16<4, 1>,
                         cudaFuncAttributeMaxDynamicSharedMemorySize, KV_SMEM_BYTES);
    cudaFuncSetAttribute(gemm_bf16<20, 0>,
                         cudaFuncAttributeMaxDynamicSharedMemorySize, KV_SMEM_BYTES);
    cudaFuncSetAttribute(gemm_bf16<6, 2>,
                         cudaFuncAttributeMaxDynamicSharedMemorySize, KV_SMEM_BYTES);

    setup_kernel<<<1, 256>>>(batch, mask);
    cvt_kernel<<<8192, 160>>>(emb);
    transpose_bf16<<<dim3(DIM / 32, HDH / 32), 256>>>(Wq, DIM, HDH, p_wqg, 0);
    transpose_bf16<<<dim3(DIM / 32, HDH / 32), 256>>>(Wg, DIM, HDH, p_wqg, 384);
    transpose_bf16<<<dim3(D_SEQ / 32, HDH / 32), 256>>>(Wk, D_SEQ, HDH, p_wt, 0);
    transpose_bf16<<<dim3(D_SEQ / 32, HDH / 32), 256>>>(Wv, D_SEQ, HDH, p_wt, 384);
    transpose_bf16<<<dim3(HDH / 32, DIM / 32), 256>>>(Wback, HDH, DIM, p_wbt, 0);
    ln_kernel<<<N_NODE / 8, 256>>>(node, ln_g, ln_b);
    gemm_bf16<4, 1><<<dim3(16, 12), 256, KV_SMEM_BYTES>>>(
        p_y, p_wqg, p_qb, p_gpre, bg, nullptr);
    gemm_bf16<20, 0><<<dim3(64, 12), 256, KV_SMEM_BYTES>>>(
        p_embt, p_wt, p_kb, p_vt, nullptr, nullptr);
    attn_kernel<<<288, 256, ATTN_SMEM_BYTES>>>();
    gf_kernel<<<N_NODE * HDH / (8 * 256), 256>>>();
    gemm_bf16<6, 2><<<dim3(16, 4), 256, KV_SMEM_BYTES>>>(
        p_gf, p_wbt, out, nullptr, node, bback);
}